// round 9
// baseline (speedup 1.0000x reference)
#include <cuda_runtime.h>

#define NQ    12
#define DIM   4096
#define NL    4
#define NT    256
#define KPT   16
// Buffer A swizzle: preserves bit0 (float4-safe), conflict-free for its patterns
#define SWA(i) ((i) ^ ((((i) >> 4) & 7) << 1))
// Buffer B swizzle (R8-verified for pass0-store / pass1-gather)
#define SWB(i) ((i) ^ (((i) >> 4) & 0xF))

struct cplx { float x, y; };

__device__ __forceinline__ cplx cmul(cplx a, cplx b) {
    return { a.x*b.x - a.y*b.y, a.x*b.y + a.y*b.x };
}
__device__ __forceinline__ cplx cadd(cplx a, cplx b) {
    return { a.x + b.x, a.y + b.y };
}
__device__ __forceinline__ void mmul(const cplx* A, const cplx* B, cplx* C) {
    C[0] = cadd(cmul(A[0], B[0]), cmul(A[1], B[2]));
    C[1] = cadd(cmul(A[0], B[1]), cmul(A[1], B[3]));
    C[2] = cadd(cmul(A[2], B[0]), cmul(A[3], B[2]));
    C[3] = cadd(cmul(A[2], B[1]), cmul(A[3], B[3]));
}
__device__ __forceinline__ cplx eph(float2 e, int bit) {
    return { e.x, bit ? -e.y : e.y };
}

// real RY rotation on local register bit m of v[16]
__device__ __forceinline__ void apply_ry(float2 v[KPT], float c, float s, int m) {
    #pragma unroll
    for (int h = 0; h < 8; h++) {
        const int k0 = ((h >> m) << (m + 1)) | (h & ((1 << m) - 1));
        const int k1 = k0 | (1 << m);
        const float2 s0 = v[k0];
        const float2 s1 = v[k1];
        v[k0].x = c*s0.x - s*s1.x;
        v[k0].y = c*s0.y - s*s1.y;
        v[k1].x = s*s0.x + c*s1.x;
        v[k1].y = s*s0.y + c*s1.y;
    }
}

extern __shared__ float2 dsm[];   // [0,DIM): buffer A, [DIM,2*DIM): buffer B

__global__ __launch_bounds__(NT, 2)
void qsim_kernel(const float* __restrict__ x,
                 const float* __restrict__ params,
                 float* __restrict__ out)
{
    float2* __restrict__ Ast = dsm;
    float2* __restrict__ Bst = dsm + DIM;

    __shared__ float2 RYcs[NL][NQ];
    __shared__ float2 EG[NL][NQ], EA[NL][NQ];
    __shared__ float2 TA2[NL-1][2][16];
    __shared__ float2 TBt[NL-1][32];
    __shared__ float2 TCt[NL-1][16];
    __shared__ float  red[NT / 32];

    const int t = threadIdx.x;
    const int b = blockIdx.x;

    // ---- phase 1: 48 fused gates + ZYZ decomposition ----
    if (t < NL * NQ) {
        const int l = t / NQ;
        const int q = t % NQ;
        const float xv = x[b];
        const float x1 = asinf(xv);
        const float x2 = acosf(xv * xv);

        float c, s;
        sincosf(0.5f * x1, &s, &c);
        cplx RY[4]  = { {c,0.f}, {-s,0.f}, {s,0.f}, {c,0.f} };
        sincosf(0.5f * x2, &s, &c);
        cplx RZ[4]  = { {c,-s}, {0.f,0.f}, {0.f,0.f}, {c,s} };

        const float t0 = params[q * (NL * 3) + l * 3 + 0];
        const float t1 = params[q * (NL * 3) + l * 3 + 1];
        const float t2 = params[q * (NL * 3) + l * 3 + 2];

        sincosf(0.5f * t0, &s, &c);
        cplx RX0[4] = { {c,0.f}, {0.f,-s}, {0.f,-s}, {c,0.f} };
        sincosf(0.5f * t1, &s, &c);
        cplx RZ1[4] = { {c,-s}, {0.f,0.f}, {0.f,0.f}, {c,s} };
        sincosf(0.5f * t2, &s, &c);
        cplx RX2[4] = { {c,0.f}, {0.f,-s}, {0.f,-s}, {c,0.f} };

        cplx A[4], B[4];
        mmul(RZ,  RY, A);
        mmul(RX0, A,  B);
        mmul(RZ1, B,  A);
        mmul(RX2, A,  B);   // fused U in SU(2)

        // ZYZ: U = RZ(alpha) RY(theta) RZ(gamma)
        const float cc = sqrtf(B[0].x*B[0].x + B[0].y*B[0].y);
        const float ss = sqrtf(B[2].x*B[2].x + B[2].y*B[2].y);
        RYcs[l][q] = make_float2(cc, ss);
        const float aa = atan2f(-B[0].y, B[0].x);
        const float bb = atan2f( B[2].y, B[2].x);
        float sg, cg, sa, ca;
        sincosf(0.5f * (aa - bb), &sg, &cg);
        sincosf(0.5f * (aa + bb), &sa, &ca);
        EG[l][q] = make_float2(cg, -sg);
        EA[l][q] = make_float2(ca, -sa);
    }
    __syncthreads();

    // ---- phase 2: fused boundary diagonals D(i) = gamma_{bd+1}(i)*alpha_bd(g(i)) ----
    if (t < (NL - 1) * 80) {
        const int bd = t / 80;
        const int r  = t % 80;
        cplx d = {1.f, 0.f};
        if (r < 32) {
            const int c7 = r >> 4;
            const int k  = r & 15;
            const int k3 = (k >> 3) & 1, k2 = (k >> 2) & 1, k1 = (k >> 1) & 1, k0 = k & 1;
            d = cmul(d, eph(EG[bd+1][0], k3));  d = cmul(d, eph(EA[bd][0], k3));
            d = cmul(d, eph(EG[bd+1][1], k2));  d = cmul(d, eph(EA[bd][1], k2 ^ k3));
            d = cmul(d, eph(EG[bd+1][2], k1));  d = cmul(d, eph(EA[bd][2], k1 ^ k2));
            d = cmul(d, eph(EG[bd+1][3], k0));  d = cmul(d, eph(EA[bd][3], k0 ^ k1));
            d = cmul(d, eph(EG[bd+1][4], c7));  d = cmul(d, eph(EA[bd][4], c7 ^ k0));
            TA2[bd][c7][k] = make_float2(d.x, d.y);
        } else if (r < 64) {
            const int u = r - 32;
            const int u4 = (u >> 4) & 1, u3 = (u >> 3) & 1, u2 = (u >> 2) & 1,
                      u1 = (u >> 1) & 1, u0 = u & 1;
            d = cmul(d, eph(EG[bd+1][5], u3));  d = cmul(d, eph(EA[bd][5], u3 ^ u4));
            d = cmul(d, eph(EG[bd+1][6], u2));  d = cmul(d, eph(EA[bd][6], u2 ^ u3));
            d = cmul(d, eph(EG[bd+1][7], u1));  d = cmul(d, eph(EA[bd][7], u1 ^ u2));
            d = cmul(d, eph(EG[bd+1][8], u0));  d = cmul(d, eph(EA[bd][8], u0 ^ u1));
            TBt[bd][u] = make_float2(d.x, d.y);
        } else {
            const int w = r - 64;
            const int w3 = (w >> 3) & 1, w2 = (w >> 2) & 1, w1 = (w >> 1) & 1, w0 = w & 1;
            d = cmul(d, eph(EG[bd+1][9],  w2)); d = cmul(d, eph(EA[bd][9],  w2 ^ w3));
            d = cmul(d, eph(EG[bd+1][10], w1)); d = cmul(d, eph(EA[bd][10], w1 ^ w2));
            d = cmul(d, eph(EG[bd+1][11], w0)); d = cmul(d, eph(EA[bd][11], w0 ^ w1));
            TCt[bd][w] = make_float2(d.x, d.y);
        }
    }
    __syncthreads();

    float2 v[KPT];

    #define RY_PASS(L, P)                                                     \
        {                                                                     \
            _Pragma("unroll")                                                 \
            for (int m = 0; m < 4; m++) {                                     \
                const float2 cs = RYcs[L][4*(P) + 3 - m];                     \
                apply_ry(v, cs.x, cs.y, m);                                   \
            }                                                                 \
        }

    // ======== layer 0: real Kronecker column -> buffer A (float4 stores) ====
    {
        float w = 1.f;
        #pragma unroll
        for (int q = 0; q < 8; q++) {
            const float2 cs = RYcs[0][q];
            w *= ((t >> (7 - q)) & 1) ? cs.y : cs.x;
        }
        const float2 c8 = RYcs[0][8], c9 = RYcs[0][9], c10 = RYcs[0][10], c11 = RYcs[0][11];
        const int base = t << 4;
        #pragma unroll
        for (int j = 0; j < 8; j++) {
            const int k0 = 2 * j, k1 = 2 * j + 1;
            const float col0 = ((k0 & 8) ? c8.y : c8.x) * ((k0 & 4) ? c9.y : c9.x) *
                               ((k0 & 2) ? c10.y : c10.x) * ((k0 & 1) ? c11.y : c11.x);
            const float col1 = ((k1 & 8) ? c8.y : c8.x) * ((k1 & 4) ? c9.y : c9.x) *
                               ((k1 & 2) ? c10.y : c10.x) * ((k1 & 1) ? c11.y : c11.x);
            *(float4*)&Ast[SWA(base | k0)] = make_float4(w * col0, 0.f, w * col1, 0.f);
        }
        __syncthreads();
    }

    // ======== layers 1..3 ========
    for (int l = 1; l < NL; l++) {
        const int bd = l - 1;

        // pass 0: perm-gather from A (+fused boundary diag), store -> B (ping-pong)
        {
            const float2 tb = TBt[bd][(t >> 3) & 31];
            const float2 tc = TCt[bd][t & 15];
            const cplx  sc = cmul(cplx{tb.x, tb.y}, cplx{tc.x, tc.y});
            const float2* ta = &TA2[bd][(t >> 7) & 1][0];
            #pragma unroll
            for (int k = 0; k < KPT; k++) {
                const int i = (k << 8) | t;
                const int j = i ^ (i >> 1);
                const float2 s0 = Ast[SWA(j)];
                const float2 a  = ta[k];
                const cplx  d  = cmul(sc, cplx{a.x, a.y});
                v[k].x = d.x*s0.x - d.y*s0.y;
                v[k].y = d.x*s0.y + d.y*s0.x;
            }
            RY_PASS(l, 0)
            #pragma unroll
            for (int k = 0; k < KPT; k++) Bst[SWB((k << 8) | t)] = v[k];
            __syncthreads();
        }

        // pass 1 (bits 7..4): gather B, store -> A
        {
            const int base = ((t & 0xF0) << 4) | (t & 0x0F);
            #pragma unroll
            for (int k = 0; k < KPT; k++) v[k] = Bst[SWB(base | (k << 4))];
            RY_PASS(l, 1)
            #pragma unroll
            for (int k = 0; k < KPT; k++) Ast[SWA(base | (k << 4))] = v[k];
            __syncthreads();
        }

        // pass 2 (bits 3..0): in-place on A, float4
        {
            const int base = t << 4;
            #pragma unroll
            for (int j = 0; j < 8; j++) {
                const float4 w = *(const float4*)&Ast[SWA(base | (2 * j))];
                v[2*j]   = make_float2(w.x, w.y);
                v[2*j+1] = make_float2(w.z, w.w);
            }
            RY_PASS(l, 2)
            if (l < NL - 1) {
                #pragma unroll
                for (int j = 0; j < 8; j++) {
                    *(float4*)&Ast[SWA(base | (2 * j))] =
                        make_float4(v[2*j].x, v[2*j].y, v[2*j+1].x, v[2*j+1].y);
                }
                __syncthreads();
            }
            // last layer: stay in registers. CNOT perm preserves bit 11; the
            // dropped alpha_3 diagonal is modulus-preserving.
        }
    }

    // ---- <Z_0>: sign = bit 11 of i = (t<<4)|k -> bit 7 of t ----
    float acc = 0.f;
    #pragma unroll
    for (int k = 0; k < KPT; k++)
        acc += v[k].x * v[k].x + v[k].y * v[k].y;
    acc = (t & 0x80) ? -acc : acc;

    #pragma unroll
    for (int o = 16; o > 0; o >>= 1) acc += __shfl_xor_sync(0xffffffffu, acc, o);
    if ((t & 31) == 0) red[t >> 5] = acc;
    __syncthreads();
    if (t < 32) {
        float v2 = (t < NT / 32) ? red[t] : 0.f;
        #pragma unroll
        for (int o = 4; o > 0; o >>= 1) v2 += __shfl_xor_sync(0xffffffffu, v2, o);
        if (t == 0) out[b] = v2;
    }
}

extern "C" void kernel_launch(void* const* d_in, const int* in_sizes, int n_in,
                              void* d_out, int out_size)
{
    const float* x      = (const float*)d_in[0];
    const float* params = (const float*)d_in[1];
    if (n_in >= 2 && in_sizes[0] != 256 && in_sizes[1] == 256) {
        x      = (const float*)d_in[1];
        params = (const float*)d_in[0];
    }
    float* out = (float*)d_out;

    const size_t smem = (size_t)(2 * DIM) * sizeof(float2);   // 64 KB dynamic
    static bool attr_set = false;
    if (!attr_set) {
        cudaFuncSetAttribute(qsim_kernel, cudaFuncAttributeMaxDynamicSharedMemorySize,
                             (int)smem);
        attr_set = true;
    }
    qsim_kernel<<<256, NT, smem>>>(x, params, out);
}

// round 10
// speedup vs baseline: 1.2650x; 1.2650x over previous
#include <cuda_runtime.h>

#define NQ    12
#define DIM   4096
#define NL    4
#define NT    256
#define KPT   16
// Buffer A swizzle: preserves bit0 (float4-safe)
#define SWA(i) ((i) ^ ((((i) >> 4) & 7) << 1))
// Buffer B swizzle
#define SWB(i) ((i) ^ (((i) >> 4) & 0xF))

struct cplx { float x, y; };

__device__ __forceinline__ cplx cmul(cplx a, cplx b) {
    return { a.x*b.x - a.y*b.y, a.x*b.y + a.y*b.x };
}
__device__ __forceinline__ cplx cadd(cplx a, cplx b) {
    return { a.x + b.x, a.y + b.y };
}
__device__ __forceinline__ void mmul(const cplx* A, const cplx* B, cplx* C) {
    C[0] = cadd(cmul(A[0], B[0]), cmul(A[1], B[2]));
    C[1] = cadd(cmul(A[0], B[1]), cmul(A[1], B[3]));
    C[2] = cadd(cmul(A[2], B[0]), cmul(A[3], B[2]));
    C[3] = cadd(cmul(A[2], B[1]), cmul(A[3], B[3]));
}
__device__ __forceinline__ cplx eph(float2 e, int bit) {
    return { e.x, bit ? -e.y : e.y };
}

// real RY rotation on local register bit m of v[16]
__device__ __forceinline__ void apply_ry(float2 v[KPT], float c, float s, int m) {
    #pragma unroll
    for (int h = 0; h < 8; h++) {
        const int k0 = ((h >> m) << (m + 1)) | (h & ((1 << m) - 1));
        const int k1 = k0 | (1 << m);
        const float2 s0 = v[k0];
        const float2 s1 = v[k1];
        v[k0].x = c*s0.x - s*s1.x;
        v[k0].y = c*s0.y - s*s1.y;
        v[k1].x = s*s0.x + c*s1.x;
        v[k1].y = s*s0.y + c*s1.y;
    }
}

extern __shared__ float2 dsm[];   // [0,DIM): buffer A, [DIM,2*DIM): buffer B

__global__ __launch_bounds__(NT, 2)
void qsim_kernel(const float* __restrict__ x,
                 const float* __restrict__ params,
                 float* __restrict__ out)
{
    float2* __restrict__ Ast = dsm;
    float2* __restrict__ Bst = dsm + DIM;

    __shared__ float2 RYcs[NL][NQ];
    __shared__ float2 EG[NL][NQ], EA[NL][NQ];
    __shared__ float2 TA2[NL-1][2][16];
    __shared__ float2 TBt[NL-1][32];
    __shared__ float2 TCt[NL-1][16];
    __shared__ float2 E3[2][8];      // layer-3 relative phase: TA2[2][c7][k|8]*conj(TA2[2][c7][k])
    __shared__ float  red[NT / 32];

    const int t = threadIdx.x;
    const int b = blockIdx.x;

    // ---- phase 1: 48 fused gates + ZYZ decomposition ----
    if (t < NL * NQ) {
        const int l = t / NQ;
        const int q = t % NQ;
        const float xv = x[b];
        const float x1 = asinf(xv);
        const float x2 = acosf(xv * xv);

        float c, s;
        sincosf(0.5f * x1, &s, &c);
        cplx RY[4]  = { {c,0.f}, {-s,0.f}, {s,0.f}, {c,0.f} };
        sincosf(0.5f * x2, &s, &c);
        cplx RZ[4]  = { {c,-s}, {0.f,0.f}, {0.f,0.f}, {c,s} };

        const float t0 = params[q * (NL * 3) + l * 3 + 0];
        const float t1 = params[q * (NL * 3) + l * 3 + 1];
        const float t2 = params[q * (NL * 3) + l * 3 + 2];

        sincosf(0.5f * t0, &s, &c);
        cplx RX0[4] = { {c,0.f}, {0.f,-s}, {0.f,-s}, {c,0.f} };
        sincosf(0.5f * t1, &s, &c);
        cplx RZ1[4] = { {c,-s}, {0.f,0.f}, {0.f,0.f}, {c,s} };
        sincosf(0.5f * t2, &s, &c);
        cplx RX2[4] = { {c,0.f}, {0.f,-s}, {0.f,-s}, {c,0.f} };

        cplx A[4], B[4];
        mmul(RZ,  RY, A);
        mmul(RX0, A,  B);
        mmul(RZ1, B,  A);
        mmul(RX2, A,  B);   // fused U in SU(2)

        // ZYZ: U = RZ(alpha) RY(theta) RZ(gamma)
        const float cc = sqrtf(B[0].x*B[0].x + B[0].y*B[0].y);
        const float ss = sqrtf(B[2].x*B[2].x + B[2].y*B[2].y);
        RYcs[l][q] = make_float2(cc, ss);
        const float aa = atan2f(-B[0].y, B[0].x);
        const float bb = atan2f( B[2].y, B[2].x);
        float sg, cg, sa, ca;
        sincosf(0.5f * (aa - bb), &sg, &cg);
        sincosf(0.5f * (aa + bb), &sa, &ca);
        EG[l][q] = make_float2(cg, -sg);
        EA[l][q] = make_float2(ca, -sa);
    }
    __syncthreads();

    // ---- phase 2: fused boundary diagonals D(i) = gamma_{bd+1}(i)*alpha_bd(g(i)) ----
    if (t < (NL - 1) * 80) {
        const int bd = t / 80;
        const int r  = t % 80;
        cplx d = {1.f, 0.f};
        if (r < 32) {
            const int c7 = r >> 4;
            const int k  = r & 15;
            const int k3 = (k >> 3) & 1, k2 = (k >> 2) & 1, k1 = (k >> 1) & 1, k0 = k & 1;
            d = cmul(d, eph(EG[bd+1][0], k3));  d = cmul(d, eph(EA[bd][0], k3));
            d = cmul(d, eph(EG[bd+1][1], k2));  d = cmul(d, eph(EA[bd][1], k2 ^ k3));
            d = cmul(d, eph(EG[bd+1][2], k1));  d = cmul(d, eph(EA[bd][2], k1 ^ k2));
            d = cmul(d, eph(EG[bd+1][3], k0));  d = cmul(d, eph(EA[bd][3], k0 ^ k1));
            d = cmul(d, eph(EG[bd+1][4], c7));  d = cmul(d, eph(EA[bd][4], c7 ^ k0));
            TA2[bd][c7][k] = make_float2(d.x, d.y);
        } else if (r < 64) {
            const int u = r - 32;
            const int u4 = (u >> 4) & 1, u3 = (u >> 3) & 1, u2 = (u >> 2) & 1,
                      u1 = (u >> 1) & 1, u0 = u & 1;
            d = cmul(d, eph(EG[bd+1][5], u3));  d = cmul(d, eph(EA[bd][5], u3 ^ u4));
            d = cmul(d, eph(EG[bd+1][6], u2));  d = cmul(d, eph(EA[bd][6], u2 ^ u3));
            d = cmul(d, eph(EG[bd+1][7], u1));  d = cmul(d, eph(EA[bd][7], u1 ^ u2));
            d = cmul(d, eph(EG[bd+1][8], u0));  d = cmul(d, eph(EA[bd][8], u0 ^ u1));
            TBt[bd][u] = make_float2(d.x, d.y);
        } else {
            const int w = r - 64;
            const int w3 = (w >> 3) & 1, w2 = (w >> 2) & 1, w1 = (w >> 1) & 1, w0 = w & 1;
            d = cmul(d, eph(EG[bd+1][9],  w2)); d = cmul(d, eph(EA[bd][9],  w2 ^ w3));
            d = cmul(d, eph(EG[bd+1][10], w1)); d = cmul(d, eph(EA[bd][10], w1 ^ w2));
            d = cmul(d, eph(EG[bd+1][11], w0)); d = cmul(d, eph(EA[bd][11], w0 ^ w1));
            TCt[bd][w] = make_float2(d.x, d.y);
        }
    }
    __syncthreads();

    // ---- phase 2b: layer-3 relative phases e = TA2[2][c7][k|8] * conj(TA2[2][c7][k]) ----
    if (t < 16) {
        const int c7 = t >> 3;
        const int k  = t & 7;
        const float2 d1 = TA2[2][c7][k | 8];
        const float2 d0 = TA2[2][c7][k];
        E3[c7][k] = make_float2(d1.x*d0.x + d1.y*d0.y, d1.y*d0.x - d1.x*d0.y);
    }
    __syncthreads();

    float2 v[KPT];

    #define RY_PASS(L, P)                                                     \
        {                                                                     \
            _Pragma("unroll")                                                 \
            for (int m = 0; m < 4; m++) {                                     \
                const float2 cs = RYcs[L][4*(P) + 3 - m];                     \
                apply_ry(v, cs.x, cs.y, m);                                   \
            }                                                                 \
        }

    // ======== layer 0: real Kronecker column -> buffer A (float4 stores) ====
    {
        float w = 1.f;
        #pragma unroll
        for (int q = 0; q < 8; q++) {
            const float2 cs = RYcs[0][q];
            w *= ((t >> (7 - q)) & 1) ? cs.y : cs.x;
        }
        const float2 c8 = RYcs[0][8], c9 = RYcs[0][9], c10 = RYcs[0][10], c11 = RYcs[0][11];
        const int base = t << 4;
        #pragma unroll
        for (int j = 0; j < 8; j++) {
            const int k0 = 2 * j, k1 = 2 * j + 1;
            const float col0 = ((k0 & 8) ? c8.y : c8.x) * ((k0 & 4) ? c9.y : c9.x) *
                               ((k0 & 2) ? c10.y : c10.x) * ((k0 & 1) ? c11.y : c11.x);
            const float col1 = ((k1 & 8) ? c8.y : c8.x) * ((k1 & 4) ? c9.y : c9.x) *
                               ((k1 & 2) ? c10.y : c10.x) * ((k1 & 1) ? c11.y : c11.x);
            *(float4*)&Ast[SWA(base | k0)] = make_float4(w * col0, 0.f, w * col1, 0.f);
        }
        __syncthreads();
    }

    // ======== layers 1..2 (full) ========
    for (int l = 1; l <= 2; l++) {
        const int bd = l - 1;

        // pass 0: perm-gather from A (+fused boundary diag), store -> B
        {
            const float2 tb = TBt[bd][(t >> 3) & 31];
            const float2 tc = TCt[bd][t & 15];
            const cplx  sc = cmul(cplx{tb.x, tb.y}, cplx{tc.x, tc.y});
            const float2* ta = &TA2[bd][(t >> 7) & 1][0];
            #pragma unroll
            for (int k = 0; k < KPT; k++) {
                const int i = (k << 8) | t;
                const int j = i ^ (i >> 1);
                const float2 s0 = Ast[SWA(j)];
                const float2 a  = ta[k];
                const cplx  d  = cmul(sc, cplx{a.x, a.y});
                v[k].x = d.x*s0.x - d.y*s0.y;
                v[k].y = d.x*s0.y + d.y*s0.x;
            }
            RY_PASS(l, 0)
            #pragma unroll
            for (int k = 0; k < KPT; k++) Bst[SWB((k << 8) | t)] = v[k];
            __syncthreads();
        }

        // pass 1 (bits 7..4): gather B, store -> A
        {
            const int base = ((t & 0xF0) << 4) | (t & 0x0F);
            #pragma unroll
            for (int k = 0; k < KPT; k++) v[k] = Bst[SWB(base | (k << 4))];
            RY_PASS(l, 1)
            #pragma unroll
            for (int k = 0; k < KPT; k++) Ast[SWA(base | (k << 4))] = v[k];
            __syncthreads();
        }

        // pass 2 (bits 3..0): in-place on A, float4 (always store: next layer reads)
        {
            const int base = t << 4;
            #pragma unroll
            for (int j = 0; j < 8; j++) {
                const float4 w = *(const float4*)&Ast[SWA(base | (2 * j))];
                v[2*j]   = make_float2(w.x, w.y);
                v[2*j+1] = make_float2(w.z, w.w);
            }
            RY_PASS(l, 2)
            #pragma unroll
            for (int j = 0; j < 8; j++) {
                *(float4*)&Ast[SWA(base | (2 * j))] =
                    make_float4(v[2*j].x, v[2*j].y, v[2*j+1].x, v[2*j+1].y);
            }
            __syncthreads();
        }
    }

    // ======== layer 3 collapsed: only qubit-0's RY affects <Z_0> ========
    // Norms per bit-11 class are invariant under: alpha_3 diag, RYs on qubits
    // 1..11, and the final CNOT perm. Remaining: perm-gather + relative phase
    // e (class ratio of the boundary diag) + RY(bit11) butterfly + |.|^2 sums.
    float acc = 0.f;
    {
        const float2 cs = RYcs[3][0];           // (cos, sin) of qubit-0 theta/2
        const float2* e3 = &E3[(t >> 7) & 1][0];
        #pragma unroll
        for (int k = 0; k < 8; k++) {
            const int i0 = (k << 8) | t;              // bit11 = 0
            const int i1 = ((k | 8) << 8) | t;        // bit11 = 1
            const float2 s0 = Ast[SWA(i0 ^ (i0 >> 1))];
            const float2 s1 = Ast[SWA(i1 ^ (i1 >> 1))];
            const float2 e  = e3[k];
            // es1 = e * s1 (relative phase of class-1 vs class-0 diag factors)
            const float ex = e.x*s1.x - e.y*s1.y;
            const float ey = e.x*s1.y + e.y*s1.x;
            // RY butterfly on bit 11
            const float r0x = cs.x*s0.x - cs.y*ex;
            const float r0y = cs.x*s0.y - cs.y*ey;
            const float r1x = cs.y*s0.x + cs.x*ex;
            const float r1y = cs.y*s0.y + cs.x*ey;
            acc += (r0x*r0x + r0y*r0y) - (r1x*r1x + r1y*r1y);
        }
    }

    #pragma unroll
    for (int o = 16; o > 0; o >>= 1) acc += __shfl_xor_sync(0xffffffffu, acc, o);
    if ((t & 31) == 0) red[t >> 5] = acc;
    __syncthreads();
    if (t < 32) {
        float v2 = (t < NT / 32) ? red[t] : 0.f;
        #pragma unroll
        for (int o = 4; o > 0; o >>= 1) v2 += __shfl_xor_sync(0xffffffffu, v2, o);
        if (t == 0) out[b] = v2;
    }
}

extern "C" void kernel_launch(void* const* d_in, const int* in_sizes, int n_in,
                              void* d_out, int out_size)
{
    const float* x      = (const float*)d_in[0];
    const float* params = (const float*)d_in[1];
    if (n_in >= 2 && in_sizes[0] != 256 && in_sizes[1] == 256) {
        x      = (const float*)d_in[1];
        params = (const float*)d_in[0];
    }
    float* out = (float*)d_out;

    const size_t smem = (size_t)(2 * DIM) * sizeof(float2);   // 64 KB dynamic
    static bool attr_set = false;
    if (!attr_set) {
        cudaFuncSetAttribute(qsim_kernel, cudaFuncAttributeMaxDynamicSharedMemorySize,
                             (int)smem);
        attr_set = true;
    }
    qsim_kernel<<<256, NT, smem>>>(x, params, out);
}